// round 1
// baseline (speedup 1.0000x reference)
#include <cuda_runtime.h>
#include <math.h>

// Problem constants
#define BATCH 2
#define SEQ 2048
#define EMB 2048
#define NHEAD 16
#define HDIM 128
#define THREE_E 6144
#define MROWS (BATCH * SEQ)   // 4096

// Scratch (device globals — no cudaMalloc allowed)
__device__ float g_qkv[(size_t)MROWS * THREE_E];   // [B*S, 3E]  (Q|K|V interleaved per reference reshape)
__device__ float g_attn[(size_t)MROWS * EMB];      // [B*S, E]   attention output (head-merged)

// ---------------------------------------------------------------------------
// Generic GEMM: C[M,N] = A[M,K] * Bw[N,K]^T + bias[N]
// Both operands K-contiguous (row-major A, row-major weight [N,K]).
// 128x128 block tile, BK=16, 256 threads, 8x8 per-thread register tile.
// ---------------------------------------------------------------------------
#define BM 128
#define BN 128
#define BK 16
#define TM 8
#define TN 8

__global__ __launch_bounds__(256)
void gemm_abt_bias(const float* __restrict__ A,
                   const float* __restrict__ Bw,
                   const float* __restrict__ bias,
                   float* __restrict__ C,
                   int M, int N, int K)
{
    __shared__ float As[BK][BM];
    __shared__ float Bs[BK][BN];

    const int tid  = threadIdx.x;
    const int tcol = tid & 15;   // 0..15 -> N direction
    const int trow = tid >> 4;   // 0..15 -> M direction
    const long m0 = (long)blockIdx.y * BM;
    const long n0 = (long)blockIdx.x * BN;

    float acc[TM][TN];
#pragma unroll
    for (int i = 0; i < TM; ++i)
#pragma unroll
        for (int j = 0; j < TN; ++j) acc[i][j] = 0.0f;

    for (int k0 = 0; k0 < K; k0 += BK) {
        // Load tiles (each thread: 2 float4 from A, 2 from Bw), store transposed [k][row]
#pragma unroll
        for (int i = 0; i < 2; ++i) {
            int s   = tid + i * 256;        // 0..511
            int row = s >> 2;               // 0..127
            int kq  = (s & 3) << 2;         // 0,4,8,12
            float4 av = *(const float4*)(A  + (m0 + row) * (long)K + k0 + kq);
            As[kq + 0][row] = av.x; As[kq + 1][row] = av.y;
            As[kq + 2][row] = av.z; As[kq + 3][row] = av.w;
            float4 bv = *(const float4*)(Bw + (n0 + row) * (long)K + k0 + kq);
            Bs[kq + 0][row] = bv.x; Bs[kq + 1][row] = bv.y;
            Bs[kq + 2][row] = bv.z; Bs[kq + 3][row] = bv.w;
        }
        __syncthreads();

#pragma unroll
        for (int k = 0; k < BK; ++k) {
            float4 a0 = *(const float4*)&As[k][trow * TM];
            float4 a1 = *(const float4*)&As[k][trow * TM + 4];
            float4 b0 = *(const float4*)&Bs[k][tcol * TN];
            float4 b1 = *(const float4*)&Bs[k][tcol * TN + 4];
            float ar[8] = {a0.x, a0.y, a0.z, a0.w, a1.x, a1.y, a1.z, a1.w};
            float br[8] = {b0.x, b0.y, b0.z, b0.w, b1.x, b1.y, b1.z, b1.w};
#pragma unroll
            for (int i = 0; i < TM; ++i)
#pragma unroll
                for (int j = 0; j < TN; ++j)
                    acc[i][j] = fmaf(ar[i], br[j], acc[i][j]);
        }
        __syncthreads();
    }

    // Epilogue: add bias, write float4
    float bb[8];
#pragma unroll
    for (int j = 0; j < TN; ++j) bb[j] = bias[n0 + tcol * TN + j];

#pragma unroll
    for (int i = 0; i < TM; ++i) {
        long m = m0 + trow * TM + i;
        float4 o0, o1;
        o0.x = acc[i][0] + bb[0]; o0.y = acc[i][1] + bb[1];
        o0.z = acc[i][2] + bb[2]; o0.w = acc[i][3] + bb[3];
        o1.x = acc[i][4] + bb[4]; o1.y = acc[i][5] + bb[5];
        o1.z = acc[i][6] + bb[6]; o1.w = acc[i][7] + bb[7];
        *(float4*)(C + m * (long)N + n0 + tcol * TN)     = o0;
        *(float4*)(C + m * (long)N + n0 + tcol * TN + 4) = o1;
    }
}

// ---------------------------------------------------------------------------
// Flash attention (causal), fp32. One CTA per (q-tile, head, batch).
// Tiles: 64 q-rows x 64 k-cols, Dh=128. 256 threads = 16x16.
// Q,K stored transposed in smem ([d][s]) -> QK^T inner loop is 2x LDS.128 + 16 FFMA.
// Causal: only iterate kt <= qi (skips ~half the work).
// ---------------------------------------------------------------------------
#define FQ 64
#define FK 64

__global__ __launch_bounds__(256)
void flash_attn_causal(const float* __restrict__ qkv, float* __restrict__ out)
{
    extern __shared__ float sm[];
    float* Qst = sm;                     // [128][64]
    float* Kst = Qst + HDIM * FQ;        // [128][64]
    float* Vs  = Kst + HDIM * FK;        // [64][128]
    float* Ps  = Vs  + FK * HDIM;        // [64][64]  (q-major)

    const int qi = blockIdx.x;           // q-tile 0..31
    const int h  = blockIdx.y;
    const int b  = blockIdx.z;
    const int tid = threadIdx.x;
    const int tx = tid & 15;             // k-col / v-col group
    const int ty = tid >> 4;             // q-row group
    const int q0 = qi * FQ;

    const float scale = 0.0883883476483184f; // 1/sqrt(128)
    const float* baseQ = qkv + ((long)b * SEQ) * THREE_E + h * HDIM;
    const float* baseK = baseQ + EMB;
    const float* baseV = baseQ + 2 * EMB;

    // Load Q tile transposed: Qst[d][s]
#pragma unroll
    for (int i = 0; i < 8; ++i) {
        int slot = tid + i * 256;        // 0..2047 float4 slots
        int s = slot & 63;
        int d = (slot >> 6) << 2;        // 0..124
        float4 v = *(const float4*)(baseQ + (long)(q0 + s) * THREE_E + d);
        Qst[(d + 0) * FQ + s] = v.x;
        Qst[(d + 1) * FQ + s] = v.y;
        Qst[(d + 2) * FQ + s] = v.z;
        Qst[(d + 3) * FQ + s] = v.w;
    }

    float o[4][8];
#pragma unroll
    for (int i = 0; i < 4; ++i)
#pragma unroll
        for (int j = 0; j < 8; ++j) o[i][j] = 0.0f;
    float m_i[4] = {-INFINITY, -INFINITY, -INFINITY, -INFINITY};
    float l_i[4] = {0.f, 0.f, 0.f, 0.f};

    for (int kt = 0; kt <= qi; ++kt) {
        __syncthreads();   // previous iter done reading Kst/Vs/Ps

        // Load K tile transposed, V tile natural
#pragma unroll
        for (int i = 0; i < 8; ++i) {
            int slot = tid + i * 256;
            int s = slot & 63;
            int d = (slot >> 6) << 2;
            float4 v = *(const float4*)(baseK + (long)(kt * FK + s) * THREE_E + d);
            Kst[(d + 0) * FK + s] = v.x;
            Kst[(d + 1) * FK + s] = v.y;
            Kst[(d + 2) * FK + s] = v.z;
            Kst[(d + 3) * FK + s] = v.w;
        }
#pragma unroll
        for (int i = 0; i < 8; ++i) {
            int slot = tid + i * 256;
            int d = (slot & 31) << 2;    // 0..124
            int s = slot >> 5;           // 0..63
            float4 v = *(const float4*)(baseV + (long)(kt * FK + s) * THREE_E + d);
            *(float4*)&Vs[s * HDIM + d] = v;
        }
        __syncthreads();

        // S = Q K^T  (4x4 per thread)
        float sc[4][4];
#pragma unroll
        for (int i = 0; i < 4; ++i)
#pragma unroll
            for (int j = 0; j < 4; ++j) sc[i][j] = 0.0f;

#pragma unroll 8
        for (int d = 0; d < HDIM; ++d) {
            float4 a = *(const float4*)&Qst[d * FQ + ty * 4];
            float4 bq = *(const float4*)&Kst[d * FK + tx * 4];
            float ar[4] = {a.x, a.y, a.z, a.w};
            float br[4] = {bq.x, bq.y, bq.z, bq.w};
#pragma unroll
            for (int i = 0; i < 4; ++i)
#pragma unroll
                for (int j = 0; j < 4; ++j)
                    sc[i][j] = fmaf(ar[i], br[j], sc[i][j]);
        }

        const bool diag = (kt == qi);

        // scale + causal mask + online softmax per row
#pragma unroll
        for (int i = 0; i < 4; ++i) {
            int r = ty * 4 + i;
            float rm = -INFINITY;
#pragma unroll
            for (int j = 0; j < 4; ++j) {
                float v = sc[i][j] * scale;
                if (diag && (tx * 4 + j > r)) v = -INFINITY;
                sc[i][j] = v;
                rm = fmaxf(rm, v);
            }
            // reduce max across the 16 lanes covering this row
#pragma unroll
            for (int off = 1; off < 16; off <<= 1)
                rm = fmaxf(rm, __shfl_xor_sync(0xffffffffu, rm, off));

            float mnew = fmaxf(m_i[i], rm);
            float corr = __expf(m_i[i] - mnew);
            m_i[i] = mnew;

            float psum = 0.0f;
#pragma unroll
            for (int j = 0; j < 4; ++j) {
                float p = __expf(sc[i][j] - mnew);
                sc[i][j] = p;
                psum += p;
            }
#pragma unroll
            for (int off = 1; off < 16; off <<= 1)
                psum += __shfl_xor_sync(0xffffffffu, psum, off);

            l_i[i] = l_i[i] * corr + psum;
#pragma unroll
            for (int j = 0; j < 8; ++j) o[i][j] *= corr;

            // store P row chunk (float4, contiguous in k)
            float4 pv = make_float4(sc[i][0], sc[i][1], sc[i][2], sc[i][3]);
            *(float4*)&Ps[r * FK + tx * 4] = pv;
        }
        __syncthreads();

        // O += P @ V   (4x8 per thread over kk=0..63)
#pragma unroll 4
        for (int kk = 0; kk < FK; ++kk) {
            float4 v0 = *(const float4*)&Vs[kk * HDIM + tx * 8];
            float4 v1 = *(const float4*)&Vs[kk * HDIM + tx * 8 + 4];
            float vr[8] = {v0.x, v0.y, v0.z, v0.w, v1.x, v1.y, v1.z, v1.w};
            float pr[4];
#pragma unroll
            for (int i = 0; i < 4; ++i) pr[i] = Ps[(ty * 4 + i) * FK + kk];  // broadcast across tx
#pragma unroll
            for (int i = 0; i < 4; ++i)
#pragma unroll
                for (int j = 0; j < 8; ++j)
                    o[i][j] = fmaf(pr[i], vr[j], o[i][j]);
        }
    }

    // Normalize + write to g_attn[b*S + q, h*128 + d]
#pragma unroll
    for (int i = 0; i < 4; ++i) {
        long row = (long)b * SEQ + q0 + ty * 4 + i;
        float inv = 1.0f / l_i[i];
        float4 o0, o1;
        o0.x = o[i][0] * inv; o0.y = o[i][1] * inv; o0.z = o[i][2] * inv; o0.w = o[i][3] * inv;
        o1.x = o[i][4] * inv; o1.y = o[i][5] * inv; o1.z = o[i][6] * inv; o1.w = o[i][7] * inv;
        float* dst = out + row * EMB + h * HDIM + tx * 8;
        *(float4*)(dst)     = o0;
        *(float4*)(dst + 4) = o1;
    }
}

// ---------------------------------------------------------------------------
// Host launcher
// ---------------------------------------------------------------------------
extern "C" void kernel_launch(void* const* d_in, const int* in_sizes, int n_in,
                              void* d_out, int out_size)
{
    const float* x     = (const float*)d_in[0];   // [2,2048,2048]
    const float* Wqkv  = (const float*)d_in[1];   // [6144,2048]
    const float* bqkv  = (const float*)d_in[2];   // [6144]
    const float* Wout  = (const float*)d_in[3];   // [2048,2048]
    const float* bout  = (const float*)d_in[4];   // [2048]
    // d_in[5] = attn_mask (causal, hardcoded)
    float* out = (float*)d_out;

    float *qkvp = nullptr, *attnp = nullptr;
    cudaGetSymbolAddress((void**)&qkvp, g_qkv);
    cudaGetSymbolAddress((void**)&attnp, g_attn);

    // 1) QKV projection: [4096,6144]
    {
        dim3 grid(THREE_E / BN, MROWS / BM);
        gemm_abt_bias<<<grid, 256>>>(x, Wqkv, bqkv, qkvp, MROWS, THREE_E, EMB);
    }

    // 2) Flash attention
    {
        size_t smem = (size_t)(HDIM * FQ + HDIM * FK + FK * HDIM + FQ * FK) * sizeof(float); // 112 KB
        cudaFuncSetAttribute(flash_attn_causal, cudaFuncAttributeMaxDynamicSharedMemorySize, (int)smem);
        dim3 grid(SEQ / FQ, NHEAD, BATCH);
        flash_attn_causal<<<grid, 256, smem>>>(qkvp, attnp);
    }

    // 3) Output projection: [4096,2048]
    {
        dim3 grid(EMB / BN, MROWS / BM);
        gemm_abt_bias<<<grid, 256>>>(attnp, Wout, bout, out, MROWS, EMB, EMB);
    }
}

// round 3
// speedup vs baseline: 1.8861x; 1.8861x over previous
#include <cuda_runtime.h>
#include <math.h>
#include <stdint.h>

// Problem constants
#define BATCH 2
#define SEQ 2048
#define EMB 2048
#define NHEAD 16
#define HDIM 128
#define THREE_E 6144
#define MROWS (BATCH * SEQ)   // 4096
#define GK 2048               // K dim of both GEMMs

// Scratch (device globals — no cudaMalloc allowed)
__device__ float g_qkv[(size_t)MROWS * THREE_E];   // [B*S, 3E]
__device__ float g_attn[(size_t)MROWS * EMB];      // [B*S, E] (tf32-rounded)
__device__ float g_xr[(size_t)MROWS * EMB];        // tf32-rounded x
__device__ float g_wqkvr[(size_t)THREE_E * EMB];   // tf32-rounded W_qkv
__device__ float g_woutr[(size_t)EMB * EMB];       // tf32-rounded W_out

// ===========================================================================
// Helpers
// ===========================================================================
__device__ __forceinline__ uint32_t smem_u32(const void* p) {
    uint32_t a;
    asm("{ .reg .u64 t; cvta.to.shared.u64 t, %1; cvt.u32.u64 %0, t; }"
        : "=r"(a) : "l"(p));
    return a;
}

__device__ __forceinline__ float rna_tf32(float x) {
    uint32_t u;
    asm("cvt.rna.tf32.f32 %0, %1;" : "=r"(u) : "f"(x));
    return __uint_as_float(u);
}

#define CP_ASYNC16(dst, src) \
    asm volatile("cp.async.cg.shared.global [%0], [%1], 16;" :: "r"(dst), "l"(src))
#define CP_COMMIT() asm volatile("cp.async.commit_group;" ::: "memory")
#define CP_WAIT(n)  asm volatile("cp.async.wait_group %0;" :: "n"(n) : "memory")

// mma.sync m16n8k8 tf32: D = A*B + C   (A 16x8 row, B 8x8 col)
__device__ __forceinline__ void mma_tf32(float& d0, float& d1, float& d2, float& d3,
                                         uint32_t a0, uint32_t a1, uint32_t a2, uint32_t a3,
                                         uint32_t b0, uint32_t b1,
                                         float c0, float c1, float c2, float c3) {
    asm volatile(
        "mma.sync.aligned.m16n8k8.row.col.f32.tf32.tf32.f32 "
        "{%0,%1,%2,%3}, {%4,%5,%6,%7}, {%8,%9}, {%10,%11,%12,%13};"
        : "=f"(d0), "=f"(d1), "=f"(d2), "=f"(d3)
        : "r"(a0), "r"(a1), "r"(a2), "r"(a3), "r"(b0), "r"(b1),
          "f"(c0), "f"(c1), "f"(c2), "f"(c3));
}

// ===========================================================================
// tf32 rounding kernel (elementwise, float4)
// ===========================================================================
__global__ __launch_bounds__(256)
void round_tf32_kernel(const float* __restrict__ in, float* __restrict__ out, int n4)
{
    int i = blockIdx.x * 256 + threadIdx.x;
    if (i >= n4) return;
    float4 v = ((const float4*)in)[i];
    v.x = rna_tf32(v.x); v.y = rna_tf32(v.y);
    v.z = rna_tf32(v.z); v.w = rna_tf32(v.w);
    ((float4*)out)[i] = v;
}

// ===========================================================================
// tf32 mma.sync GEMM: C[M,N] = A[M,K] * Bw[N,K]^T + bias[N]
// CTA 128x128, BK=32, 3-stage cp.async pipeline, 8 warps (2x4), warp 64x32.
// Smem rows padded to 36 floats (stride mod 32 == 4) -> conflict-free frags.
// ===========================================================================
#define BKC 32
#define SROW 36                               // padded row stride (floats)
#define STAGE_FLOATS (128 * SROW)             // per A or B tile
#define STAGE_BYTES  (2 * STAGE_FLOATS * 4)   // A + B = 36864
#define NSTG 3
#define GEMM_SMEM (NSTG * STAGE_BYTES)        // 110592

__device__ __forceinline__ void gemm_load_stage(
    int tid, float* stage,
    const float* __restrict__ Ab, const float* __restrict__ Bb)
{
    uint32_t sa = smem_u32(stage);
    uint32_t sb = sa + STAGE_FLOATS * 4;
#pragma unroll
    for (int it = 0; it < 4; ++it) {
        int idx = tid + it * 256;      // 0..1023
        int row = idx >> 3;            // 0..127
        int c   = idx & 7;             // float4 chunk
        CP_ASYNC16(sa + row * (SROW * 4) + c * 16, Ab + (long)row * GK + c * 4);
        CP_ASYNC16(sb + row * (SROW * 4) + c * 16, Bb + (long)row * GK + c * 4);
    }
    CP_COMMIT();
}

__global__ __launch_bounds__(256, 1)
void gemm_tf32_mma(const float* __restrict__ A, const float* __restrict__ Bw,
                   const float* __restrict__ bias, float* __restrict__ C, int N)
{
    extern __shared__ float sm[];

    const int tid  = threadIdx.x;
    const int wid  = tid >> 5;
    const int lane = tid & 31;
    const int wm   = wid & 1;          // 0..1  -> 64 rows each
    const int wn   = wid >> 1;         // 0..3  -> 32 cols each
    const int lr   = lane >> 2;        // 0..7
    const int lc   = lane & 3;         // 0..3
    const long m0 = (long)blockIdx.y * 128;
    const long n0 = (long)blockIdx.x * 128;

    const float* Abase = A  + m0 * GK;
    const float* Bbase = Bw + n0 * GK;

    float acc[4][4][4];
#pragma unroll
    for (int i = 0; i < 4; ++i)
#pragma unroll
        for (int j = 0; j < 4; ++j)
#pragma unroll
            for (int q = 0; q < 4; ++q) acc[i][j][q] = 0.0f;

    // Prologue: stages 0,1
    gemm_load_stage(tid, sm + 0 * (STAGE_BYTES / 4), Abase, Bbase);
    gemm_load_stage(tid, sm + 1 * (STAGE_BYTES / 4), Abase + BKC, Bbase + BKC);

    const int KT = GK / BKC;   // 64
    for (int kt = 0; kt < KT; ++kt) {
        CP_WAIT(1);
        __syncthreads();

        const float* stage = sm + (kt % NSTG) * (STAGE_BYTES / 4);
        const uint32_t* As = (const uint32_t*)stage;
        const uint32_t* Bs = (const uint32_t*)(stage + STAGE_FLOATS);

#pragma unroll
        for (int k = 0; k < 4; ++k) {          // 4 x k8 steps
            const int k0 = k * 8;
            uint32_t af[4][4], bf[4][2];
#pragma unroll
            for (int mt = 0; mt < 4; ++mt) {
                const int rm = wm * 64 + mt * 16 + lr;
                af[mt][0] = As[(rm    ) * SROW + k0 + lc    ];
                af[mt][1] = As[(rm + 8) * SROW + k0 + lc    ];
                af[mt][2] = As[(rm    ) * SROW + k0 + lc + 4];
                af[mt][3] = As[(rm + 8) * SROW + k0 + lc + 4];
            }
#pragma unroll
            for (int nt = 0; nt < 4; ++nt) {
                const int rn = wn * 32 + nt * 8 + lr;
                bf[nt][0] = Bs[rn * SROW + k0 + lc    ];
                bf[nt][1] = Bs[rn * SROW + k0 + lc + 4];
            }
#pragma unroll
            for (int mt = 0; mt < 4; ++mt)
#pragma unroll
                for (int nt = 0; nt < 4; ++nt)
                    mma_tf32(acc[mt][nt][0], acc[mt][nt][1], acc[mt][nt][2], acc[mt][nt][3],
                             af[mt][0], af[mt][1], af[mt][2], af[mt][3],
                             bf[nt][0], bf[nt][1],
                             acc[mt][nt][0], acc[mt][nt][1], acc[mt][nt][2], acc[mt][nt][3]);
        }

        // Issue load for stage kt+2
        const int nf = kt + 2;
        if (nf < KT) {
            gemm_load_stage(tid, sm + (nf % NSTG) * (STAGE_BYTES / 4),
                            Abase + (long)nf * BKC, Bbase + (long)nf * BKC);
        } else {
            CP_COMMIT();   // keep group accounting uniform
        }
    }

    // Epilogue: write C + bias. Thread (mt,nt): rows lr, lr+8; cols 2*lc, 2*lc+1.
#pragma unroll
    for (int mt = 0; mt < 4; ++mt) {
        const long r0 = m0 + wm * 64 + mt * 16 + lr;
#pragma unroll
        for (int nt = 0; nt < 4; ++nt) {
            const long cc = n0 + wn * 32 + nt * 8 + 2 * lc;
            const float b0 = bias[cc], b1 = bias[cc + 1];
            float2 v0 = make_float2(acc[mt][nt][0] + b0, acc[mt][nt][1] + b1);
            float2 v1 = make_float2(acc[mt][nt][2] + b0, acc[mt][nt][3] + b1);
            *(float2*)(C + r0 * N + cc)       = v0;
            *(float2*)(C + (r0 + 8) * N + cc) = v1;
        }
    }
}

// ===========================================================================
// Flash attention (causal), fp32 — unchanged except tf32-rounded writeback.
// ===========================================================================
#define FQ 64
#define FK 64

__global__ __launch_bounds__(256)
void flash_attn_causal(const float* __restrict__ qkv, float* __restrict__ out)
{
    extern __shared__ float smf[];
    float* Qst = smf;                    // [128][64]
    float* Kst = Qst + HDIM * FQ;        // [128][64]
    float* Vs  = Kst + HDIM * FK;        // [64][128]
    float* Ps  = Vs  + FK * HDIM;        // [64][64]

    const int qi = blockIdx.x;
    const int h  = blockIdx.y;
    const int b  = blockIdx.z;
    const int tid = threadIdx.x;
    const int tx = tid & 15;
    const int ty = tid >> 4;
    const int q0 = qi * FQ;

    const float scale = 0.0883883476483184f; // 1/sqrt(128)
    const float* baseQ = qkv + ((long)b * SEQ) * THREE_E + h * HDIM;
    const float* baseK = baseQ + EMB;
    const float* baseV = baseQ + 2 * EMB;

#pragma unroll
    for (int i = 0; i < 8; ++i) {
        int slot = tid + i * 256;
        int s = slot & 63;
        int d = (slot >> 6) << 2;
        float4 v = *(const float4*)(baseQ + (long)(q0 + s) * THREE_E + d);
        Qst[(d + 0) * FQ + s] = v.x;
        Qst[(d + 1) * FQ + s] = v.y;
        Qst[(d + 2) * FQ + s] = v.z;
        Qst[(d + 3) * FQ + s] = v.w;
    }

    float o[4][8];
#pragma unroll
    for (int i = 0; i < 4; ++i)
#pragma unroll
        for (int j = 0; j < 8; ++j) o[i][j] = 0.0f;
    float m_i[4] = {-INFINITY, -INFINITY, -INFINITY, -INFINITY};
    float l_i[4] = {0.f, 0.f, 0.f, 0.f};

    for (int kt = 0; kt <= qi; ++kt) {
        __syncthreads();

#pragma unroll
        for (int i = 0; i < 8; ++i) {
            int slot = tid + i * 256;
            int s = slot & 63;
            int d = (slot >> 6) << 2;
            float4 v = *(const float4*)(baseK + (long)(kt * FK + s) * THREE_E + d);
            Kst[(d + 0) * FK + s] = v.x;
            Kst[(d + 1) * FK + s] = v.y;
            Kst[(d + 2) * FK + s] = v.z;
            Kst[(d + 3) * FK + s] = v.w;
        }
#pragma unroll
        for (int i = 0; i < 8; ++i) {
            int slot = tid + i * 256;
            int d = (slot & 31) << 2;
            int s = slot >> 5;
            float4 v = *(const float4*)(baseV + (long)(kt * FK + s) * THREE_E + d);
            *(float4*)&Vs[s * HDIM + d] = v;
        }
        __syncthreads();

        float sc[4][4];
#pragma unroll
        for (int i = 0; i < 4; ++i)
#pragma unroll
            for (int j = 0; j < 4; ++j) sc[i][j] = 0.0f;

#pragma unroll 8
        for (int d = 0; d < HDIM; ++d) {
            float4 a = *(const float4*)&Qst[d * FQ + ty * 4];
            float4 bq = *(const float4*)&Kst[d * FK + tx * 4];
            float ar[4] = {a.x, a.y, a.z, a.w};
            float br[4] = {bq.x, bq.y, bq.z, bq.w};
#pragma unroll
            for (int i = 0; i < 4; ++i)
#pragma unroll
                for (int j = 0; j < 4; ++j)
                    sc[i][j] = fmaf(ar[i], br[j], sc[i][j]);
        }

        const bool diag = (kt == qi);

#pragma unroll
        for (int i = 0; i < 4; ++i) {
            int r = ty * 4 + i;
            float rm = -INFINITY;
#pragma unroll
            for (int j = 0; j < 4; ++j) {
                float v = sc[i][j] * scale;
                if (diag && (tx * 4 + j > r)) v = -INFINITY;
                sc[i][j] = v;
                rm = fmaxf(rm, v);
            }
#pragma unroll
            for (int off = 1; off < 16; off <<= 1)
                rm = fmaxf(rm, __shfl_xor_sync(0xffffffffu, rm, off));

            float mnew = fmaxf(m_i[i], rm);
            float corr = __expf(m_i[i] - mnew);
            m_i[i] = mnew;

            float psum = 0.0f;
#pragma unroll
            for (int j = 0; j < 4; ++j) {
                float p = __expf(sc[i][j] - mnew);
                sc[i][j] = p;
                psum += p;
            }
#pragma unroll
            for (int off = 1; off < 16; off <<= 1)
                psum += __shfl_xor_sync(0xffffffffu, psum, off);

            l_i[i] = l_i[i] * corr + psum;
#pragma unroll
            for (int j = 0; j < 8; ++j) o[i][j] *= corr;

            float4 pv = make_float4(sc[i][0], sc[i][1], sc[i][2], sc[i][3]);
            *(float4*)&Ps[r * FK + tx * 4] = pv;
        }
        __syncthreads();

#pragma unroll 4
        for (int kk = 0; kk < FK; ++kk) {
            float4 v0 = *(const float4*)&Vs[kk * HDIM + tx * 8];
            float4 v1 = *(const float4*)&Vs[kk * HDIM + tx * 8 + 4];
            float vr[8] = {v0.x, v0.y, v0.z, v0.w, v1.x, v1.y, v1.z, v1.w};
            float pr[4];
#pragma unroll
            for (int i = 0; i < 4; ++i) pr[i] = Ps[(ty * 4 + i) * FK + kk];
#pragma unroll
            for (int i = 0; i < 4; ++i)
#pragma unroll
                for (int j = 0; j < 8; ++j)
                    o[i][j] = fmaf(pr[i], vr[j], o[i][j]);
        }
    }

#pragma unroll
    for (int i = 0; i < 4; ++i) {
        long row = (long)b * SEQ + q0 + ty * 4 + i;
        float inv = 1.0f / l_i[i];
        float4 o0, o1;
        o0.x = rna_tf32(o[i][0] * inv); o0.y = rna_tf32(o[i][1] * inv);
        o0.z = rna_tf32(o[i][2] * inv); o0.w = rna_tf32(o[i][3] * inv);
        o1.x = rna_tf32(o[i][4] * inv); o1.y = rna_tf32(o[i][5] * inv);
        o1.z = rna_tf32(o[i][6] * inv); o1.w = rna_tf32(o[i][7] * inv);
        float* dst = out + row * EMB + h * HDIM + tx * 8;
        *(float4*)(dst)     = o0;
        *(float4*)(dst + 4) = o1;
    }
}

// ===========================================================================
// Host launcher
// ===========================================================================
extern "C" void kernel_launch(void* const* d_in, const int* in_sizes, int n_in,
                              void* d_out, int out_size)
{
    const float* x     = (const float*)d_in[0];   // [2,2048,2048]
    const float* Wqkv  = (const float*)d_in[1];   // [6144,2048]
    const float* bqkv  = (const float*)d_in[2];   // [6144]
    const float* Wout  = (const float*)d_in[3];   // [2048,2048]
    const float* bout  = (const float*)d_in[4];   // [2048]
    float* out = (float*)d_out;

    float *qkvp, *attnp, *xr, *wqkvr, *woutr;
    cudaGetSymbolAddress((void**)&qkvp,  g_qkv);
    cudaGetSymbolAddress((void**)&attnp, g_attn);
    cudaGetSymbolAddress((void**)&xr,    g_xr);
    cudaGetSymbolAddress((void**)&wqkvr, g_wqkvr);
    cudaGetSymbolAddress((void**)&woutr, g_woutr);

    // 0) tf32 pre-rounding (unbiased RNA) of all tensor-core GEMM operands
    {
        int n4x = MROWS * EMB / 4;
        int n4q = THREE_E * EMB / 4;
        int n4o = EMB * EMB / 4;
        round_tf32_kernel<<<(n4x + 255) / 256, 256>>>(x, xr, n4x);
        round_tf32_kernel<<<(n4q + 255) / 256, 256>>>(Wqkv, wqkvr, n4q);
        round_tf32_kernel<<<(n4o + 255) / 256, 256>>>(Wout, woutr, n4o);
    }

    cudaFuncSetAttribute(gemm_tf32_mma, cudaFuncAttributeMaxDynamicSharedMemorySize, GEMM_SMEM);

    // 1) QKV projection: [4096,6144] = xr @ Wqkv^T + bqkv
    {
        dim3 grid(THREE_E / 128, MROWS / 128);   // 48 x 32
        gemm_tf32_mma<<<grid, 256, GEMM_SMEM>>>(xr, wqkvr, bqkv, qkvp, THREE_E);
    }

    // 2) Flash attention (fp32)
    {
        size_t smem = (size_t)(HDIM * FQ + HDIM * FK + FK * HDIM + FQ * FK) * sizeof(float);
        cudaFuncSetAttribute(flash_attn_causal, cudaFuncAttributeMaxDynamicSharedMemorySize, (int)smem);
        dim3 grid(SEQ / FQ, NHEAD, BATCH);
        flash_attn_causal<<<grid, 256, smem>>>(qkvp, attnp);
    }

    // 3) Output projection: [4096,2048] = attn @ Wout^T + bout
    {
        dim3 grid(EMB / 128, MROWS / 128);       // 16 x 32
        gemm_tf32_mma<<<grid, 256, GEMM_SMEM>>>(attnp, woutr, bout, out, EMB);
    }
}

// round 4
// speedup vs baseline: 2.9095x; 1.5426x over previous
#include <cuda_runtime.h>
#include <math.h>
#include <stdint.h>

// Problem constants
#define BATCH 2
#define SEQ 2048
#define EMB 2048
#define NHEAD 16
#define HDIM 128
#define THREE_E 6144
#define MROWS (BATCH * SEQ)   // 4096
#define GK 2048               // K dim of both GEMMs

// Scratch (device globals — no cudaMalloc allowed)
__device__ float g_qkv[(size_t)MROWS * THREE_E];   // [B*S, 3E]
__device__ float g_attn[(size_t)MROWS * EMB];      // [B*S, E] (tf32-rounded)
__device__ float g_xr[(size_t)MROWS * EMB];        // tf32-rounded x
__device__ float g_wqkvr[(size_t)THREE_E * EMB];   // tf32-rounded W_qkv
__device__ float g_woutr[(size_t)EMB * EMB];       // tf32-rounded W_out

// ===========================================================================
// Helpers
// ===========================================================================
__device__ __forceinline__ uint32_t smem_u32(const void* p) {
    uint32_t a;
    asm("{ .reg .u64 t; cvta.to.shared.u64 t, %1; cvt.u32.u64 %0, t; }"
        : "=r"(a) : "l"(p));
    return a;
}

__device__ __forceinline__ float rna_tf32(float x) {
    uint32_t u;
    asm("cvt.rna.tf32.f32 %0, %1;" : "=r"(u) : "f"(x));
    return __uint_as_float(u);
}

#define CP_ASYNC16(dst, src) \
    asm volatile("cp.async.cg.shared.global [%0], [%1], 16;" :: "r"(dst), "l"(src))
#define CP_COMMIT() asm volatile("cp.async.commit_group;" ::: "memory")
#define CP_WAIT(n)  asm volatile("cp.async.wait_group %0;" :: "n"(n) : "memory")

// mma.sync m16n8k8 tf32: D = A*B + C   (A 16x8 row, B 8x8 col)
__device__ __forceinline__ void mma_tf32(float& d0, float& d1, float& d2, float& d3,
                                         uint32_t a0, uint32_t a1, uint32_t a2, uint32_t a3,
                                         uint32_t b0, uint32_t b1,
                                         float c0, float c1, float c2, float c3) {
    asm volatile(
        "mma.sync.aligned.m16n8k8.row.col.f32.tf32.tf32.f32 "
        "{%0,%1,%2,%3}, {%4,%5,%6,%7}, {%8,%9}, {%10,%11,%12,%13};"
        : "=f"(d0), "=f"(d1), "=f"(d2), "=f"(d3)
        : "r"(a0), "r"(a1), "r"(a2), "r"(a3), "r"(b0), "r"(b1),
          "f"(c0), "f"(c1), "f"(c2), "f"(c3));
}

// ===========================================================================
// tf32 rounding kernel (elementwise, float4)
// ===========================================================================
__global__ __launch_bounds__(256)
void round_tf32_kernel(const float* __restrict__ in, float* __restrict__ out, int n4)
{
    int i = blockIdx.x * 256 + threadIdx.x;
    if (i >= n4) return;
    float4 v = ((const float4*)in)[i];
    v.x = rna_tf32(v.x); v.y = rna_tf32(v.y);
    v.z = rna_tf32(v.z); v.w = rna_tf32(v.w);
    ((float4*)out)[i] = v;
}

// ===========================================================================
// tf32 mma.sync GEMM: C[M,N] = A[M,K] * Bw[N,K]^T + bias[N]   (unchanged R3)
// ===========================================================================
#define BKC 32
#define SROW 36
#define STAGE_FLOATS (128 * SROW)
#define STAGE_BYTES  (2 * STAGE_FLOATS * 4)
#define NSTG 3
#define GEMM_SMEM (NSTG * STAGE_BYTES)

__device__ __forceinline__ void gemm_load_stage(
    int tid, float* stage,
    const float* __restrict__ Ab, const float* __restrict__ Bb)
{
    uint32_t sa = smem_u32(stage);
    uint32_t sb = sa + STAGE_FLOATS * 4;
#pragma unroll
    for (int it = 0; it < 4; ++it) {
        int idx = tid + it * 256;
        int row = idx >> 3;
        int c   = idx & 7;
        CP_ASYNC16(sa + row * (SROW * 4) + c * 16, Ab + (long)row * GK + c * 4);
        CP_ASYNC16(sb + row * (SROW * 4) + c * 16, Bb + (long)row * GK + c * 4);
    }
    CP_COMMIT();
}

__global__ __launch_bounds__(256, 1)
void gemm_tf32_mma(const float* __restrict__ A, const float* __restrict__ Bw,
                   const float* __restrict__ bias, float* __restrict__ C, int N)
{
    extern __shared__ float sm[];

    const int tid  = threadIdx.x;
    const int wid  = tid >> 5;
    const int lane = tid & 31;
    const int wm   = wid & 1;
    const int wn   = wid >> 1;
    const int lr   = lane >> 2;
    const int lc   = lane & 3;
    const long m0 = (long)blockIdx.y * 128;
    const long n0 = (long)blockIdx.x * 128;

    const float* Abase = A  + m0 * GK;
    const float* Bbase = Bw + n0 * GK;

    float acc[4][4][4];
#pragma unroll
    for (int i = 0; i < 4; ++i)
#pragma unroll
        for (int j = 0; j < 4; ++j)
#pragma unroll
            for (int q = 0; q < 4; ++q) acc[i][j][q] = 0.0f;

    gemm_load_stage(tid, sm + 0 * (STAGE_BYTES / 4), Abase, Bbase);
    gemm_load_stage(tid, sm + 1 * (STAGE_BYTES / 4), Abase + BKC, Bbase + BKC);

    const int KT = GK / BKC;
    for (int kt = 0; kt < KT; ++kt) {
        CP_WAIT(1);
        __syncthreads();

        const float* stage = sm + (kt % NSTG) * (STAGE_BYTES / 4);
        const uint32_t* As = (const uint32_t*)stage;
        const uint32_t* Bs = (const uint32_t*)(stage + STAGE_FLOATS);

#pragma unroll
        for (int k = 0; k < 4; ++k) {
            const int k0 = k * 8;
            uint32_t af[4][4], bf[4][2];
#pragma unroll
            for (int mt = 0; mt < 4; ++mt) {
                const int rm = wm * 64 + mt * 16 + lr;
                af[mt][0] = As[(rm    ) * SROW + k0 + lc    ];
                af[mt][1] = As[(rm + 8) * SROW + k0 + lc    ];
                af[mt][2] = As[(rm    ) * SROW + k0 + lc + 4];
                af[mt][3] = As[(rm + 8) * SROW + k0 + lc + 4];
            }
#pragma unroll
            for (int nt = 0; nt < 4; ++nt) {
                const int rn = wn * 32 + nt * 8 + lr;
                bf[nt][0] = Bs[rn * SROW + k0 + lc    ];
                bf[nt][1] = Bs[rn * SROW + k0 + lc + 4];
            }
#pragma unroll
            for (int mt = 0; mt < 4; ++mt)
#pragma unroll
                for (int nt = 0; nt < 4; ++nt)
                    mma_tf32(acc[mt][nt][0], acc[mt][nt][1], acc[mt][nt][2], acc[mt][nt][3],
                             af[mt][0], af[mt][1], af[mt][2], af[mt][3],
                             bf[nt][0], bf[nt][1],
                             acc[mt][nt][0], acc[mt][nt][1], acc[mt][nt][2], acc[mt][nt][3]);
        }

        const int nf = kt + 2;
        if (nf < KT) {
            gemm_load_stage(tid, sm + (nf % NSTG) * (STAGE_BYTES / 4),
                            Abase + (long)nf * BKC, Bbase + (long)nf * BKC);
        } else {
            CP_COMMIT();
        }
    }

#pragma unroll
    for (int mt = 0; mt < 4; ++mt) {
        const long r0 = m0 + wm * 64 + mt * 16 + lr;
#pragma unroll
        for (int nt = 0; nt < 4; ++nt) {
            const long cc = n0 + wn * 32 + nt * 8 + 2 * lc;
            const float b0 = bias[cc], b1 = bias[cc + 1];
            float2 v0 = make_float2(acc[mt][nt][0] + b0, acc[mt][nt][1] + b1);
            float2 v1 = make_float2(acc[mt][nt][2] + b0, acc[mt][nt][3] + b1);
            *(float2*)(C + r0 * N + cc)       = v0;
            *(float2*)(C + (r0 + 8) * N + cc) = v1;
        }
    }
}

// ===========================================================================
// Tensor-core flash attention (causal), tf32 mma.sync.
// CTA: 128 q-rows (8 warps x m16), k-tile 32, Dh=128.
// Scores: 3xTF32 (hi/lo split) for near-fp32 accuracy. PV: tf32 RNA.
// Smem: Qhi/Qlo [128][132], Khi/Klo [32][132], Vs [32][136], Ps [128][36].
// ===========================================================================
#define ATT_QHI 0
#define ATT_QLO 16896
#define ATT_KHI 33792
#define ATT_KLO 38016
#define ATT_VS  42240
#define ATT_PS  46592
#define ATT_SMEM_FLOATS 51200
#define ATT_SMEM_BYTES (ATT_SMEM_FLOATS * 4)   // 204800

__global__ __launch_bounds__(256, 1)
void flash_attn_tc(const float* __restrict__ qkv, float* __restrict__ out)
{
    extern __shared__ float sm[];
    float* Qhi = sm + ATT_QHI;
    float* Qlo = sm + ATT_QLO;
    float* Khi = sm + ATT_KHI;
    float* Klo = sm + ATT_KLO;
    float* Vsm = sm + ATT_VS;
    float* Psm = sm + ATT_PS;

    const int tid  = threadIdx.x;
    const int wid  = tid >> 5;
    const int lane = tid & 31;
    const int lr   = lane >> 2;          // 0..7
    const int lc   = lane & 3;           // 0..3
    const int qi   = (int)(gridDim.x - 1) - (int)blockIdx.x;  // heavy tiles first
    const int h    = blockIdx.y;
    const int b    = blockIdx.z;
    const int q0   = qi * 128;
    const int m0   = wid * 16;           // warp's q-row offset in tile

    const float SCL2E = 0.08838834764831845f * 1.4426950408889634f; // scale*log2(e)

    const float* baseQ = qkv + ((long)b * SEQ) * THREE_E + h * HDIM;
    const float* baseK = baseQ + EMB;
    const float* baseV = baseQ + 2 * EMB;

    // ---- Load Q tile with hi/lo tf32 split ----
#pragma unroll
    for (int i = 0; i < 16; ++i) {
        int slot = tid + i * 256;        // 0..4095
        int row  = slot >> 5;            // 0..127
        int d    = (slot & 31) * 4;
        float4 v = *(const float4*)(baseQ + (long)(q0 + row) * THREE_E + d);
        float4 hi, lo;
        hi.x = rna_tf32(v.x); lo.x = rna_tf32(v.x - hi.x);
        hi.y = rna_tf32(v.y); lo.y = rna_tf32(v.y - hi.y);
        hi.z = rna_tf32(v.z); lo.z = rna_tf32(v.z - hi.z);
        hi.w = rna_tf32(v.w); lo.w = rna_tf32(v.w - hi.w);
        *(float4*)(Qhi + row * 132 + d) = hi;
        *(float4*)(Qlo + row * 132 + d) = lo;
    }

    float oacc[16][4];
#pragma unroll
    for (int nt = 0; nt < 16; ++nt)
#pragma unroll
        for (int q = 0; q < 4; ++q) oacc[nt][q] = 0.0f;
    float m_lo = -1e30f, m_hi = -1e30f;
    float l_lo = 0.0f,   l_hi = 0.0f;

    const int row_lo = q0 + m0 + lr;
    const int row_hi = row_lo + 8;

    const int ktEnd = 4 * qi + 3;
    for (int kt = 0; kt <= ktEnd; ++kt) {
        __syncthreads();   // previous iteration done reading K/V smem

        // ---- Load K (hi/lo) and V (RNA) tiles ----
#pragma unroll
        for (int i = 0; i < 4; ++i) {
            int slot = tid + i * 256;    // 0..1023
            int row  = slot >> 5;        // 0..31
            int d    = (slot & 31) * 4;
            const long gr = (long)(kt * 32 + row) * THREE_E + d;
            float4 kv = *(const float4*)(baseK + gr);
            float4 hi, lo;
            hi.x = rna_tf32(kv.x); lo.x = rna_tf32(kv.x - hi.x);
            hi.y = rna_tf32(kv.y); lo.y = rna_tf32(kv.y - hi.y);
            hi.z = rna_tf32(kv.z); lo.z = rna_tf32(kv.z - hi.z);
            hi.w = rna_tf32(kv.w); lo.w = rna_tf32(kv.w - hi.w);
            *(float4*)(Khi + row * 132 + d) = hi;
            *(float4*)(Klo + row * 132 + d) = lo;
            float4 vv = *(const float4*)(baseV + gr);
            vv.x = rna_tf32(vv.x); vv.y = rna_tf32(vv.y);
            vv.z = rna_tf32(vv.z); vv.w = rna_tf32(vv.w);
            *(float4*)(Vsm + row * 136 + d) = vv;
        }
        __syncthreads();

        // Warp-tile fully masked? (all cols > all rows)  barriers stay uniform.
        if (kt * 32 > q0 + m0 + 15) continue;

        // ---- S = Q K^T via 3xTF32 ----
        float sacc[4][4];
#pragma unroll
        for (int nt = 0; nt < 4; ++nt)
#pragma unroll
            for (int q = 0; q < 4; ++q) sacc[nt][q] = 0.0f;

        const uint32_t* qh = (const uint32_t*)Qhi;
        const uint32_t* ql = (const uint32_t*)Qlo;
        const uint32_t* kh = (const uint32_t*)Khi;
        const uint32_t* kl = (const uint32_t*)Klo;

#pragma unroll
        for (int kd = 0; kd < 16; ++kd) {
            const int k0 = kd * 8;
            const int ra = (m0 + lr) * 132 + k0 + lc;
            const int rb = (m0 + lr + 8) * 132 + k0 + lc;
            uint32_t ah0 = qh[ra], ah1 = qh[rb], ah2 = qh[ra + 4], ah3 = qh[rb + 4];
            uint32_t al0 = ql[ra], al1 = ql[rb], al2 = ql[ra + 4], al3 = ql[rb + 4];
#pragma unroll
            for (int nt = 0; nt < 4; ++nt) {
                const int rk = (nt * 8 + lr) * 132 + k0 + lc;
                uint32_t bh0 = kh[rk], bh1 = kh[rk + 4];
                uint32_t bl0 = kl[rk], bl1 = kl[rk + 4];
                mma_tf32(sacc[nt][0], sacc[nt][1], sacc[nt][2], sacc[nt][3],
                         ah0, ah1, ah2, ah3, bh0, bh1,
                         sacc[nt][0], sacc[nt][1], sacc[nt][2], sacc[nt][3]);
                mma_tf32(sacc[nt][0], sacc[nt][1], sacc[nt][2], sacc[nt][3],
                         ah0, ah1, ah2, ah3, bl0, bl1,
                         sacc[nt][0], sacc[nt][1], sacc[nt][2], sacc[nt][3]);
                mma_tf32(sacc[nt][0], sacc[nt][1], sacc[nt][2], sacc[nt][3],
                         al0, al1, al2, al3, bh0, bh1,
                         sacc[nt][0], sacc[nt][1], sacc[nt][2], sacc[nt][3]);
            }
        }

        // ---- Online softmax (base-2) ----
        const bool tail = (kt >= 4 * qi);
        float rm_lo = -INFINITY, rm_hi = -INFINITY;
#pragma unroll
        for (int nt = 0; nt < 4; ++nt) {
            const int c0 = kt * 32 + nt * 8 + 2 * lc;
            float v0 = sacc[nt][0] * SCL2E;
            float v1 = sacc[nt][1] * SCL2E;
            float v2 = sacc[nt][2] * SCL2E;
            float v3 = sacc[nt][3] * SCL2E;
            if (tail) {
                if (c0     > row_lo) v0 = -INFINITY;
                if (c0 + 1 > row_lo) v1 = -INFINITY;
                if (c0     > row_hi) v2 = -INFINITY;
                if (c0 + 1 > row_hi) v3 = -INFINITY;
            }
            sacc[nt][0] = v0; sacc[nt][1] = v1;
            sacc[nt][2] = v2; sacc[nt][3] = v3;
            rm_lo = fmaxf(rm_lo, fmaxf(v0, v1));
            rm_hi = fmaxf(rm_hi, fmaxf(v2, v3));
        }
        rm_lo = fmaxf(rm_lo, __shfl_xor_sync(0xffffffffu, rm_lo, 1));
        rm_lo = fmaxf(rm_lo, __shfl_xor_sync(0xffffffffu, rm_lo, 2));
        rm_hi = fmaxf(rm_hi, __shfl_xor_sync(0xffffffffu, rm_hi, 1));
        rm_hi = fmaxf(rm_hi, __shfl_xor_sync(0xffffffffu, rm_hi, 2));

        const float mn_lo = fmaxf(m_lo, rm_lo);
        const float mn_hi = fmaxf(m_hi, rm_hi);
        const float corr_lo = exp2f(m_lo - mn_lo);
        const float corr_hi = exp2f(m_hi - mn_hi);
        m_lo = mn_lo; m_hi = mn_hi;

        float ps_lo = 0.0f, ps_hi = 0.0f;
#pragma unroll
        for (int nt = 0; nt < 4; ++nt) {
            float p0 = exp2f(sacc[nt][0] - mn_lo);
            float p1 = exp2f(sacc[nt][1] - mn_lo);
            float p2 = exp2f(sacc[nt][2] - mn_hi);
            float p3 = exp2f(sacc[nt][3] - mn_hi);
            ps_lo += p0 + p1;
            ps_hi += p2 + p3;
            // RNA-rounded P to smem (warp-private region)
            float2 w0 = make_float2(rna_tf32(p0), rna_tf32(p1));
            float2 w1 = make_float2(rna_tf32(p2), rna_tf32(p3));
            *(float2*)(Psm + (m0 + lr    ) * 36 + nt * 8 + 2 * lc) = w0;
            *(float2*)(Psm + (m0 + lr + 8) * 36 + nt * 8 + 2 * lc) = w1;
        }
        ps_lo += __shfl_xor_sync(0xffffffffu, ps_lo, 1);
        ps_lo += __shfl_xor_sync(0xffffffffu, ps_lo, 2);
        ps_hi += __shfl_xor_sync(0xffffffffu, ps_hi, 1);
        ps_hi += __shfl_xor_sync(0xffffffffu, ps_hi, 2);
        l_lo = l_lo * corr_lo + ps_lo;
        l_hi = l_hi * corr_hi + ps_hi;

#pragma unroll
        for (int nt = 0; nt < 16; ++nt) {
            oacc[nt][0] *= corr_lo; oacc[nt][1] *= corr_lo;
            oacc[nt][2] *= corr_hi; oacc[nt][3] *= corr_hi;
        }
        __syncwarp();

        // ---- O += P V ----
        const uint32_t* ps = (const uint32_t*)Psm;
        const uint32_t* vs = (const uint32_t*)Vsm;
#pragma unroll
        for (int kd = 0; kd < 4; ++kd) {
            const int k0 = kd * 8;
            const int ra = (m0 + lr) * 36 + k0 + lc;
            const int rb = (m0 + lr + 8) * 36 + k0 + lc;
            uint32_t a0 = ps[ra], a1 = ps[rb], a2 = ps[ra + 4], a3 = ps[rb + 4];
#pragma unroll
            for (int nt = 0; nt < 16; ++nt) {
                uint32_t b0 = vs[(k0 + lc    ) * 136 + nt * 8 + lr];
                uint32_t b1 = vs[(k0 + lc + 4) * 136 + nt * 8 + lr];
                mma_tf32(oacc[nt][0], oacc[nt][1], oacc[nt][2], oacc[nt][3],
                         a0, a1, a2, a3, b0, b1,
                         oacc[nt][0], oacc[nt][1], oacc[nt][2], oacc[nt][3]);
            }
        }
    }

    // ---- Normalize + write (tf32 RNA for GEMM2) ----
    const float inv_lo = 1.0f / l_lo;
    const float inv_hi = 1.0f / l_hi;
    const long grow_lo = (long)b * SEQ + row_lo;
    const long grow_hi = (long)b * SEQ + row_hi;
#pragma unroll
    for (int nt = 0; nt < 16; ++nt) {
        const int col = h * HDIM + nt * 8 + 2 * lc;
        float2 w0 = make_float2(rna_tf32(oacc[nt][0] * inv_lo),
                                rna_tf32(oacc[nt][1] * inv_lo));
        float2 w1 = make_float2(rna_tf32(oacc[nt][2] * inv_hi),
                                rna_tf32(oacc[nt][3] * inv_hi));
        *(float2*)(out + grow_lo * EMB + col) = w0;
        *(float2*)(out + grow_hi * EMB + col) = w1;
    }
}

// ===========================================================================
// Host launcher
// ===========================================================================
extern "C" void kernel_launch(void* const* d_in, const int* in_sizes, int n_in,
                              void* d_out, int out_size)
{
    const float* x     = (const float*)d_in[0];
    const float* Wqkv  = (const float*)d_in[1];
    const float* bqkv  = (const float*)d_in[2];
    const float* Wout  = (const float*)d_in[3];
    const float* bout  = (const float*)d_in[4];
    float* out = (float*)d_out;

    float *qkvp, *attnp, *xr, *wqkvr, *woutr;
    cudaGetSymbolAddress((void**)&qkvp,  g_qkv);
    cudaGetSymbolAddress((void**)&attnp, g_attn);
    cudaGetSymbolAddress((void**)&xr,    g_xr);
    cudaGetSymbolAddress((void**)&wqkvr, g_wqkvr);
    cudaGetSymbolAddress((void**)&woutr, g_woutr);

    // 0) tf32 pre-rounding of GEMM operands
    {
        int n4x = MROWS * EMB / 4;
        int n4q = THREE_E * EMB / 4;
        int n4o = EMB * EMB / 4;
        round_tf32_kernel<<<(n4x + 255) / 256, 256>>>(x, xr, n4x);
        round_tf32_kernel<<<(n4q + 255) / 256, 256>>>(Wqkv, wqkvr, n4q);
        round_tf32_kernel<<<(n4o + 255) / 256, 256>>>(Wout, woutr, n4o);
    }

    cudaFuncSetAttribute(gemm_tf32_mma, cudaFuncAttributeMaxDynamicSharedMemorySize, GEMM_SMEM);

    // 1) QKV projection
    {
        dim3 grid(THREE_E / 128, MROWS / 128);
        gemm_tf32_mma<<<grid, 256, GEMM_SMEM>>>(xr, wqkvr, bqkv, qkvp, THREE_E);
    }

    // 2) Tensor-core flash attention
    {
        cudaFuncSetAttribute(flash_attn_tc, cudaFuncAttributeMaxDynamicSharedMemorySize, ATT_SMEM_BYTES);
        dim3 grid(SEQ / 128, NHEAD, BATCH);
        flash_attn_tc<<<grid, 256, ATT_SMEM_BYTES>>>(qkvp, attnp);
    }

    // 3) Output projection
    {
        dim3 grid(EMB / 128, MROWS / 128);
        gemm_tf32_mma<<<grid, 256, GEMM_SMEM>>>(attnp, woutr, bout, out, EMB);
    }
}

// round 5
// speedup vs baseline: 3.2152x; 1.1051x over previous
#include <cuda_runtime.h>
#include <math.h>
#include <stdint.h>

// Problem constants
#define BATCH 2
#define SEQ 2048
#define EMB 2048
#define NHEAD 16
#define HDIM 128
#define THREE_E 6144
#define MROWS (BATCH * SEQ)   // 4096
#define GK 2048               // K dim of both GEMMs

// Scratch (device globals — no cudaMalloc allowed)
__device__ float g_qkv[(size_t)MROWS * THREE_E];   // [B*S, 3E]
__device__ float g_attn[(size_t)MROWS * EMB];      // [B*S, E] (tf32-rounded)
__device__ float g_xr[(size_t)MROWS * EMB];        // tf32-rounded x
__device__ float g_wqkvr[(size_t)THREE_E * EMB];   // tf32-rounded W_qkv
__device__ float g_woutr[(size_t)EMB * EMB];       // tf32-rounded W_out

// ===========================================================================
// Helpers
// ===========================================================================
__device__ __forceinline__ uint32_t smem_u32(const void* p) {
    uint32_t a;
    asm("{ .reg .u64 t; cvta.to.shared.u64 t, %1; cvt.u32.u64 %0, t; }"
        : "=r"(a) : "l"(p));
    return a;
}

__device__ __forceinline__ float rna_tf32(float x) {
    uint32_t u;
    asm("cvt.rna.tf32.f32 %0, %1;" : "=r"(u) : "f"(x));
    return __uint_as_float(u);
}

#define CP_ASYNC16(dst, src) \
    asm volatile("cp.async.cg.shared.global [%0], [%1], 16;" :: "r"(dst), "l"(src))
#define CP_COMMIT() asm volatile("cp.async.commit_group;" ::: "memory")
#define CP_WAIT(n)  asm volatile("cp.async.wait_group %0;" :: "n"(n) : "memory")

// mma.sync m16n8k8 tf32: D = A*B + C   (A 16x8 row, B 8x8 col)
__device__ __forceinline__ void mma_tf32(float& d0, float& d1, float& d2, float& d3,
                                         uint32_t a0, uint32_t a1, uint32_t a2, uint32_t a3,
                                         uint32_t b0, uint32_t b1,
                                         float c0, float c1, float c2, float c3) {
    asm volatile(
        "mma.sync.aligned.m16n8k8.row.col.f32.tf32.tf32.f32 "
        "{%0,%1,%2,%3}, {%4,%5,%6,%7}, {%8,%9}, {%10,%11,%12,%13};"
        : "=f"(d0), "=f"(d1), "=f"(d2), "=f"(d3)
        : "r"(a0), "r"(a1), "r"(a2), "r"(a3), "r"(b0), "r"(b1),
          "f"(c0), "f"(c1), "f"(c2), "f"(c3));
}

__device__ __forceinline__ void ldsm_x4(uint32_t& r0, uint32_t& r1,
                                        uint32_t& r2, uint32_t& r3, uint32_t addr) {
    asm volatile("ldmatrix.sync.aligned.m8n8.x4.shared.b16 {%0,%1,%2,%3}, [%4];"
                 : "=r"(r0), "=r"(r1), "=r"(r2), "=r"(r3) : "r"(addr));
}
__device__ __forceinline__ void ldsm_x2(uint32_t& r0, uint32_t& r1, uint32_t addr) {
    asm volatile("ldmatrix.sync.aligned.m8n8.x2.shared.b16 {%0,%1}, [%2];"
                 : "=r"(r0), "=r"(r1) : "r"(addr));
}

// ===========================================================================
// tf32 rounding kernel (elementwise, float4)
// ===========================================================================
__global__ __launch_bounds__(256)
void round_tf32_kernel(const float* __restrict__ in, float* __restrict__ out, int n4)
{
    int i = blockIdx.x * 256 + threadIdx.x;
    if (i >= n4) return;
    float4 v = ((const float4*)in)[i];
    v.x = rna_tf32(v.x); v.y = rna_tf32(v.y);
    v.z = rna_tf32(v.z); v.w = rna_tf32(v.w);
    ((float4*)out)[i] = v;
}

// ===========================================================================
// tf32 mma.sync GEMM: C[M,N] = A[M,K] * Bw[N,K]^T + bias[N]
// CTA 128x128, BK=32, 3-stage cp.async pipeline, 8 warps (2x4), warp 64x32.
// R5: ldmatrix fragments, loads issued before MMA, 2 CTAs/SM (regs<=128).
// ===========================================================================
#define BKC 32
#define SROW 36
#define STAGE_FLOATS (128 * SROW)
#define STAGE_BYTES  (2 * STAGE_FLOATS * 4)
#define NSTG 3
#define GEMM_SMEM (NSTG * STAGE_BYTES)      // 110592

__device__ __forceinline__ void gemm_load_stage(
    int tid, uint32_t sa,
    const float* __restrict__ Ab, const float* __restrict__ Bb)
{
    uint32_t sb = sa + STAGE_FLOATS * 4;
#pragma unroll
    for (int it = 0; it < 4; ++it) {
        int idx = tid + it * 256;
        int row = idx >> 3;
        int c   = idx & 7;
        CP_ASYNC16(sa + row * (SROW * 4) + c * 16, Ab + (long)row * GK + c * 4);
        CP_ASYNC16(sb + row * (SROW * 4) + c * 16, Bb + (long)row * GK + c * 4);
    }
    CP_COMMIT();
}

__global__ __launch_bounds__(256, 2)
void gemm_tf32_mma(const float* __restrict__ A, const float* __restrict__ Bw,
                   const float* __restrict__ bias, float* __restrict__ C, int N)
{
    extern __shared__ float sm[];

    const int tid  = threadIdx.x;
    const int wid  = tid >> 5;
    const int lane = tid & 31;
    const int wm   = wid & 1;
    const int wn   = wid >> 1;
    const int lr   = lane >> 2;
    const int lc   = lane & 3;
    const long m0 = (long)blockIdx.y * 128;
    const long n0 = (long)blockIdx.x * 128;

    const float* Abase = A  + m0 * GK;
    const float* Bbase = Bw + n0 * GK;

    const uint32_t smem0 = smem_u32(sm);
    // Per-thread ldmatrix base offsets (bytes)
    // A x4: row = wm*64 + mt*16 + (lane&15), col = 4*(lane>>4)
    const uint32_t aoff = ((wm * 64 + (lane & 15)) * SROW + 4 * (lane >> 4)) * 4;
    // B x2: row = wn*32 + nt*8 + (lane&7), col = 4*((lane>>3)&1)
    const uint32_t boff = ((wn * 32 + (lane & 7)) * SROW + 4 * ((lane >> 3) & 1)) * 4
                          + STAGE_FLOATS * 4;

    float acc[4][4][4];
#pragma unroll
    for (int i = 0; i < 4; ++i)
#pragma unroll
        for (int j = 0; j < 4; ++j)
#pragma unroll
            for (int q = 0; q < 4; ++q) acc[i][j][q] = 0.0f;

    gemm_load_stage(tid, smem0 + 0 * STAGE_BYTES, Abase, Bbase);
    gemm_load_stage(tid, smem0 + 1 * STAGE_BYTES, Abase + BKC, Bbase + BKC);

    const int KT = GK / BKC;   // 64
    for (int kt = 0; kt < KT; ++kt) {
        CP_WAIT(1);
        __syncthreads();

        // Issue next stage's global loads FIRST (buffer (kt+2)%3 was fully
        // consumed in iteration kt-1; the barrier above protects reuse).
        const int nf = kt + 2;
        if (nf < KT) {
            gemm_load_stage(tid, smem0 + (nf % NSTG) * STAGE_BYTES,
                            Abase + (long)nf * BKC, Bbase + (long)nf * BKC);
        } else {
            CP_COMMIT();
        }

        const uint32_t stage = smem0 + (kt % NSTG) * STAGE_BYTES;

#pragma unroll
        for (int k = 0; k < 4; ++k) {
            const uint32_t kb = k * 32;             // k0 floats -> bytes
            uint32_t af[4][4], bf[4][2];
#pragma unroll
            for (int mt = 0; mt < 4; ++mt)
                ldsm_x4(af[mt][0], af[mt][1], af[mt][2], af[mt][3],
                        stage + aoff + mt * (16 * SROW * 4) + kb);
#pragma unroll
            for (int nt = 0; nt < 4; ++nt)
                ldsm_x2(bf[nt][0], bf[nt][1],
                        stage + boff + nt * (8 * SROW * 4) + kb);
#pragma unroll
            for (int mt = 0; mt < 4; ++mt)
#pragma unroll
                for (int nt = 0; nt < 4; ++nt)
                    mma_tf32(acc[mt][nt][0], acc[mt][nt][1], acc[mt][nt][2], acc[mt][nt][3],
                             af[mt][0], af[mt][1], af[mt][2], af[mt][3],
                             bf[nt][0], bf[nt][1],
                             acc[mt][nt][0], acc[mt][nt][1], acc[mt][nt][2], acc[mt][nt][3]);
        }
    }

    // Epilogue
#pragma unroll
    for (int mt = 0; mt < 4; ++mt) {
        const long r0 = m0 + wm * 64 + mt * 16 + lr;
#pragma unroll
        for (int nt = 0; nt < 4; ++nt) {
            const long cc = n0 + wn * 32 + nt * 8 + 2 * lc;
            const float b0 = bias[cc], b1 = bias[cc + 1];
            float2 v0 = make_float2(acc[mt][nt][0] + b0, acc[mt][nt][1] + b1);
            float2 v1 = make_float2(acc[mt][nt][2] + b0, acc[mt][nt][3] + b1);
            *(float2*)(C + r0 * N + cc)       = v0;
            *(float2*)(C + (r0 + 8) * N + cc) = v1;
        }
    }
}

// ===========================================================================
// Tensor-core flash attention (causal), tf32 mma.sync.  (unchanged from R4)
// ===========================================================================
#define ATT_QHI 0
#define ATT_QLO 16896
#define ATT_KHI 33792
#define ATT_KLO 38016
#define ATT_VS  42240
#define ATT_PS  46592
#define ATT_SMEM_FLOATS 51200
#define ATT_SMEM_BYTES (ATT_SMEM_FLOATS * 4)   // 204800

__global__ __launch_bounds__(256, 1)
void flash_attn_tc(const float* __restrict__ qkv, float* __restrict__ out)
{
    extern __shared__ float sm[];
    float* Qhi = sm + ATT_QHI;
    float* Qlo = sm + ATT_QLO;
    float* Khi = sm + ATT_KHI;
    float* Klo = sm + ATT_KLO;
    float* Vsm = sm + ATT_VS;
    float* Psm = sm + ATT_PS;

    const int tid  = threadIdx.x;
    const int wid  = tid >> 5;
    const int lane = tid & 31;
    const int lr   = lane >> 2;
    const int lc   = lane & 3;
    const int qi   = (int)(gridDim.x - 1) - (int)blockIdx.x;
    const int h    = blockIdx.y;
    const int b    = blockIdx.z;
    const int q0   = qi * 128;
    const int m0   = wid * 16;

    const float SCL2E = 0.08838834764831845f * 1.4426950408889634f;

    const float* baseQ = qkv + ((long)b * SEQ) * THREE_E + h * HDIM;
    const float* baseK = baseQ + EMB;
    const float* baseV = baseQ + 2 * EMB;

#pragma unroll
    for (int i = 0; i < 16; ++i) {
        int slot = tid + i * 256;
        int row  = slot >> 5;
        int d    = (slot & 31) * 4;
        float4 v = *(const float4*)(baseQ + (long)(q0 + row) * THREE_E + d);
        float4 hi, lo;
        hi.x = rna_tf32(v.x); lo.x = rna_tf32(v.x - hi.x);
        hi.y = rna_tf32(v.y); lo.y = rna_tf32(v.y - hi.y);
        hi.z = rna_tf32(v.z); lo.z = rna_tf32(v.z - hi.z);
        hi.w = rna_tf32(v.w); lo.w = rna_tf32(v.w - hi.w);
        *(float4*)(Qhi + row * 132 + d) = hi;
        *(float4*)(Qlo + row * 132 + d) = lo;
    }

    float oacc[16][4];
#pragma unroll
    for (int nt = 0; nt < 16; ++nt)
#pragma unroll
        for (int q = 0; q < 4; ++q) oacc[nt][q] = 0.0f;
    float m_lo = -1e30f, m_hi = -1e30f;
    float l_lo = 0.0f,   l_hi = 0.0f;

    const int row_lo = q0 + m0 + lr;
    const int row_hi = row_lo + 8;

    const int ktEnd = 4 * qi + 3;
    for (int kt = 0; kt <= ktEnd; ++kt) {
        __syncthreads();

#pragma unroll
        for (int i = 0; i < 4; ++i) {
            int slot = tid + i * 256;
            int row  = slot >> 5;
            int d    = (slot & 31) * 4;
            const long gr = (long)(kt * 32 + row) * THREE_E + d;
            float4 kv = *(const float4*)(baseK + gr);
            float4 hi, lo;
            hi.x = rna_tf32(kv.x); lo.x = rna_tf32(kv.x - hi.x);
            hi.y = rna_tf32(kv.y); lo.y = rna_tf32(kv.y - hi.y);
            hi.z = rna_tf32(kv.z); lo.z = rna_tf32(kv.z - hi.z);
            hi.w = rna_tf32(kv.w); lo.w = rna_tf32(kv.w - hi.w);
            *(float4*)(Khi + row * 132 + d) = hi;
            *(float4*)(Klo + row * 132 + d) = lo;
            float4 vv = *(const float4*)(baseV + gr);
            vv.x = rna_tf32(vv.x); vv.y = rna_tf32(vv.y);
            vv.z = rna_tf32(vv.z); vv.w = rna_tf32(vv.w);
            *(float4*)(Vsm + row * 136 + d) = vv;
        }
        __syncthreads();

        if (kt * 32 > q0 + m0 + 15) continue;

        float sacc[4][4];
#pragma unroll
        for (int nt = 0; nt < 4; ++nt)
#pragma unroll
            for (int q = 0; q < 4; ++q) sacc[nt][q] = 0.0f;

        const uint32_t* qh = (const uint32_t*)Qhi;
        const uint32_t* ql = (const uint32_t*)Qlo;
        const uint32_t* kh = (const uint32_t*)Khi;
        const uint32_t* kl = (const uint32_t*)Klo;

#pragma unroll
        for (int kd = 0; kd < 16; ++kd) {
            const int k0 = kd * 8;
            const int ra = (m0 + lr) * 132 + k0 + lc;
            const int rb = (m0 + lr + 8) * 132 + k0 + lc;
            uint32_t ah0 = qh[ra], ah1 = qh[rb], ah2 = qh[ra + 4], ah3 = qh[rb + 4];
            uint32_t al0 = ql[ra], al1 = ql[rb], al2 = ql[ra + 4], al3 = ql[rb + 4];
#pragma unroll
            for (int nt = 0; nt < 4; ++nt) {
                const int rk = (nt * 8 + lr) * 132 + k0 + lc;
                uint32_t bh0 = kh[rk], bh1 = kh[rk + 4];
                uint32_t bl0 = kl[rk], bl1 = kl[rk + 4];
                mma_tf32(sacc[nt][0], sacc[nt][1], sacc[nt][2], sacc[nt][3],
                         ah0, ah1, ah2, ah3, bh0, bh1,
                         sacc[nt][0], sacc[nt][1], sacc[nt][2], sacc[nt][3]);
                mma_tf32(sacc[nt][0], sacc[nt][1], sacc[nt][2], sacc[nt][3],
                         ah0, ah1, ah2, ah3, bl0, bl1,
                         sacc[nt][0], sacc[nt][1], sacc[nt][2], sacc[nt][3]);
                mma_tf32(sacc[nt][0], sacc[nt][1], sacc[nt][2], sacc[nt][3],
                         al0, al1, al2, al3, bh0, bh1,
                         sacc[nt][0], sacc[nt][1], sacc[nt][2], sacc[nt][3]);
            }
        }

        const bool tail = (kt >= 4 * qi);
        float rm_lo = -INFINITY, rm_hi = -INFINITY;
#pragma unroll
        for (int nt = 0; nt < 4; ++nt) {
            const int c0 = kt * 32 + nt * 8 + 2 * lc;
            float v0 = sacc[nt][0] * SCL2E;
            float v1 = sacc[nt][1] * SCL2E;
            float v2 = sacc[nt][2] * SCL2E;
            float v3 = sacc[nt][3] * SCL2E;
            if (tail) {
                if (c0     > row_lo) v0 = -INFINITY;
                if (c0 + 1 > row_lo) v1 = -INFINITY;
                if (c0     > row_hi) v2 = -INFINITY;
                if (c0 + 1 > row_hi) v3 = -INFINITY;
            }
            sacc[nt][0] = v0; sacc[nt][1] = v1;
            sacc[nt][2] = v2; sacc[nt][3] = v3;
            rm_lo = fmaxf(rm_lo, fmaxf(v0, v1));
            rm_hi = fmaxf(rm_hi, fmaxf(v2, v3));
        }
        rm_lo = fmaxf(rm_lo, __shfl_xor_sync(0xffffffffu, rm_lo, 1));
        rm_lo = fmaxf(rm_lo, __shfl_xor_sync(0xffffffffu, rm_lo, 2));
        rm_hi = fmaxf(rm_hi, __shfl_xor_sync(0xffffffffu, rm_hi, 1));
        rm_hi = fmaxf(rm_hi, __shfl_xor_sync(0xffffffffu, rm_hi, 2));

        const float mn_lo = fmaxf(m_lo, rm_lo);
        const float mn_hi = fmaxf(m_hi, rm_hi);
        const float corr_lo = exp2f(m_lo - mn_lo);
        const float corr_hi = exp2f(m_hi - mn_hi);
        m_lo = mn_lo; m_hi = mn_hi;

        float ps_lo = 0.0f, ps_hi = 0.0f;
#pragma unroll
        for (int nt = 0; nt < 4; ++nt) {
            float p0 = exp2f(sacc[nt][0] - mn_lo);
            float p1 = exp2f(sacc[nt][1] - mn_lo);
            float p2 = exp2f(sacc[nt][2] - mn_hi);
            float p3 = exp2f(sacc[nt][3] - mn_hi);
            ps_lo += p0 + p1;
            ps_hi += p2 + p3;
            float2 w0 = make_float2(rna_tf32(p0), rna_tf32(p1));
            float2 w1 = make_float2(rna_tf32(p2), rna_tf32(p3));
            *(float2*)(Psm + (m0 + lr    ) * 36 + nt * 8 + 2 * lc) = w0;
            *(float2*)(Psm + (m0 + lr + 8) * 36 + nt * 8 + 2 * lc) = w1;
        }
        ps_lo += __shfl_xor_sync(0xffffffffu, ps_lo, 1);
        ps_lo += __shfl_xor_sync(0xffffffffu, ps_lo, 2);
        ps_hi += __shfl_xor_sync(0xffffffffu, ps_hi, 1);
        ps_hi += __shfl_xor_sync(0xffffffffu, ps_hi, 2);
        l_lo = l_lo * corr_lo + ps_lo;
        l_hi = l_hi * corr_hi + ps_hi;

#pragma unroll
        for (int nt = 0; nt < 16; ++nt) {
            oacc[nt][0] *= corr_lo; oacc[nt][1] *= corr_lo;
            oacc[nt][2] *= corr_hi; oacc[nt][3] *= corr_hi;
        }
        __syncwarp();

        const uint32_t* ps = (const uint32_t*)Psm;
        const uint32_t* vs = (const uint32_t*)Vsm;
#pragma unroll
        for (int kd = 0; kd < 4; ++kd) {
            const int k0 = kd * 8;
            const int ra = (m0 + lr) * 36 + k0 + lc;
            const int rb = (m0 + lr + 8) * 36 + k0 + lc;
            uint32_t a0 = ps[ra], a1 = ps[rb], a2 = ps[ra + 4], a3 = ps[rb + 4];
#pragma unroll
            for (int nt = 0; nt < 16; ++nt) {
                uint32_t b0 = vs[(k0 + lc    ) * 136 + nt * 8 + lr];
                uint32_t b1 = vs[(k0 + lc + 4) * 136 + nt * 8 + lr];
                mma_tf32(oacc[nt][0], oacc[nt][1], oacc[nt][2], oacc[nt][3],
                         a0, a1, a2, a3, b0, b1,
                         oacc[nt][0], oacc[nt][1], oacc[nt][2], oacc[nt][3]);
            }
        }
    }

    const float inv_lo = 1.0f / l_lo;
    const float inv_hi = 1.0f / l_hi;
    const long grow_lo = (long)b * SEQ + row_lo;
    const long grow_hi = (long)b * SEQ + row_hi;
#pragma unroll
    for (int nt = 0; nt < 16; ++nt) {
        const int col = h * HDIM + nt * 8 + 2 * lc;
        float2 w0 = make_float2(rna_tf32(oacc[nt][0] * inv_lo),
                                rna_tf32(oacc[nt][1] * inv_lo));
        float2 w1 = make_float2(rna_tf32(oacc[nt][2] * inv_hi),
                                rna_tf32(oacc[nt][3] * inv_hi));
        *(float2*)(out + grow_lo * EMB + col) = w0;
        *(float2*)(out + grow_hi * EMB + col) = w1;
    }
}

// ===========================================================================
// Host launcher
// ===========================================================================
extern "C" void kernel_launch(void* const* d_in, const int* in_sizes, int n_in,
                              void* d_out, int out_size)
{
    const float* x     = (const float*)d_in[0];
    const float* Wqkv  = (const float*)d_in[1];
    const float* bqkv  = (const float*)d_in[2];
    const float* Wout  = (const float*)d_in[3];
    const float* bout  = (const float*)d_in[4];
    float* out = (float*)d_out;

    float *qkvp, *attnp, *xr, *wqkvr, *woutr;
    cudaGetSymbolAddress((void**)&qkvp,  g_qkv);
    cudaGetSymbolAddress((void**)&attnp, g_attn);
    cudaGetSymbolAddress((void**)&xr,    g_xr);
    cudaGetSymbolAddress((void**)&wqkvr, g_wqkvr);
    cudaGetSymbolAddress((void**)&woutr, g_woutr);

    // 0) tf32 pre-rounding of GEMM operands
    {
        int n4x = MROWS * EMB / 4;
        int n4q = THREE_E * EMB / 4;
        int n4o = EMB * EMB / 4;
        round_tf32_kernel<<<(n4x + 255) / 256, 256>>>(x, xr, n4x);
        round_tf32_kernel<<<(n4q + 255) / 256, 256>>>(Wqkv, wqkvr, n4q);
        round_tf32_kernel<<<(n4o + 255) / 256, 256>>>(Wout, woutr, n4o);
    }

    cudaFuncSetAttribute(gemm_tf32_mma, cudaFuncAttributeMaxDynamicSharedMemorySize, GEMM_SMEM);

    // 1) QKV projection
    {
        dim3 grid(THREE_E / 128, MROWS / 128);
        gemm_tf32_mma<<<grid, 256, GEMM_SMEM>>>(xr, wqkvr, bqkv, qkvp, THREE_E);
    }

    // 2) Tensor-core flash attention
    {
        cudaFuncSetAttribute(flash_attn_tc, cudaFuncAttributeMaxDynamicSharedMemorySize, ATT_SMEM_BYTES);
        dim3 grid(SEQ / 128, NHEAD, BATCH);
        flash_attn_tc<<<grid, 256, ATT_SMEM_BYTES>>>(qkvp, attnp);
    }

    // 3) Output projection
    {
        dim3 grid(EMB / 128, MROWS / 128);
        gemm_tf32_mma<<<grid, 256, GEMM_SMEM>>>(attnp, woutr, bout, out, EMB);
    }
}